// round 10
// baseline (speedup 1.0000x reference)
#include <cuda_runtime.h>
#include <cuda_bf16.h>
#include <cstdint>

// ============================================================================
// SparseConvNet_Triplane v6: packed fma.rn.f32x2 (FFMA2) stride-1 convs.
// Accumulators paired over adjacent output channels -> weights naturally
// packed; input taps broadcast-packed once per dz slice.
// ============================================================================

#define EPSV 1e-3f

#define PACK2(dst, f)  asm("mov.b64 %0, {%1, %1};" : "=l"(dst) : "f"(f))
#define FMA2(acc, a, w) asm("fma.rn.f32x2 %0, %1, %2, %0;" : "+l"(acc) : "l"(a), "l"(w))
#define UNPACK2(lo, hi, v) asm("mov.b64 {%0, %1}, %2;" : "=f"(lo), "=f"(hi) : "l"(v))

static constexpr int N0 = 64 * 64 * 64;
static constexpr int N1 = 32 * 32 * 32;
static constexpr int N2 = 16 * 16 * 16;
static constexpr int NPTS = 65536;

static constexpr int PD0 = 66, PD0_3 = PD0 * PD0 * PD0;
static constexpr int PD1 = 34, PD1_3 = PD1 * PD1 * PD1;
static constexpr int PD2 = 18, PD2_3 = PD2 * PD2 * PD2;

// weight segments, layout [ci][k][co]
static constexpr int O_W0A = 0;
static constexpr int O_W0B = O_W0A + 16 * 32 * 27;
static constexpr int O_WD0 = O_W0B + 32 * 32 * 27;
static constexpr int O_W1A = O_WD0 + 32 * 32 * 27;
static constexpr int O_W1B = O_W1A + 32 * 64 * 27;
static constexpr int O_WD1 = O_W1B + 64 * 64 * 27;
static constexpr int O_W2A = O_WD1 + 64 * 128 * 27;
static constexpr int O_W2B = O_W2A + 128 * 128 * 27;
static constexpr int O_W2C = O_W2B + 128 * 128 * 27;
static constexpr int WT_TOTAL = O_W2C + 128 * 128 * 27;

// fused BN scale/shift segments
static constexpr int OB_0A = 0;
static constexpr int OB_0B = OB_0A + 2 * 32;
static constexpr int OB_D0 = OB_0B + 2 * 32;
static constexpr int OB_1A = OB_D0 + 2 * 32;
static constexpr int OB_1B = OB_1A + 2 * 64;
static constexpr int OB_D1 = OB_1B + 2 * 64;
static constexpr int OB_2A = OB_D1 + 2 * 128;
static constexpr int OB_2B = OB_2A + 2 * 128;
static constexpr int OB_2C = OB_2B + 2 * 128;
static constexpr int BNF_TOTAL = OB_2C + 2 * 128;

// static scratch; halos of padded buffers never written -> stay 0
__device__ __align__(16) float g_xm[16 * PD0_3];
__device__ __align__(16) float g_A0[32 * PD0_3];
__device__ __align__(16) float g_B0[32 * PD0_3];
__device__ __align__(16) float g_A1[64 * PD1_3];
__device__ __align__(16) float g_B1[64 * PD1_3];
__device__ __align__(16) float g_A2[128 * PD2_3];
__device__ __align__(16) float g_B2[128 * PD2_3];
__device__ __align__(16) float g_part[2097152];
__device__ float g_m0[N0];
__device__ float g_m1[N1];
__device__ float g_m2[N2];
__device__ __align__(16) float g_wt[WT_TOTAL];
__device__ __align__(16) float g_bnf[BNF_TOTAL];
__device__ __align__(16) float g_planes[3 * 16 * 16 * 128];
__device__ int g_mmode;

// ----------------------------------------------------------------------------
// merged prep: weight transposes + BN fusion
// ----------------------------------------------------------------------------
__global__ void prep_k(const float* __restrict__ w0a, const float* __restrict__ w0b,
                       const float* __restrict__ wd0, const float* __restrict__ w1a,
                       const float* __restrict__ w1b, const float* __restrict__ wd1,
                       const float* __restrict__ w2a, const float* __restrict__ w2b,
                       const float* __restrict__ w2c,
                       const float* __restrict__ b0a, const float* __restrict__ b0b,
                       const float* __restrict__ bd0, const float* __restrict__ b1a,
                       const float* __restrict__ b1b, const float* __restrict__ bd1,
                       const float* __restrict__ b2a, const float* __restrict__ b2b,
                       const float* __restrict__ b2c,
                       float* __restrict__ wt, float* __restrict__ bnf) {
    int i = blockIdx.x * blockDim.x + threadIdx.x;
    if (i < WT_TOTAL) {
        const float* src; int off, cin, cout;
        if      (i < O_W0B) { src = w0a; off = O_W0A; cin = 16;  cout = 32; }
        else if (i < O_WD0) { src = w0b; off = O_W0B; cin = 32;  cout = 32; }
        else if (i < O_W1A) { src = wd0; off = O_WD0; cin = 32;  cout = 32; }
        else if (i < O_W1B) { src = w1a; off = O_W1A; cin = 32;  cout = 64; }
        else if (i < O_WD1) { src = w1b; off = O_W1B; cin = 64;  cout = 64; }
        else if (i < O_W2A) { src = wd1; off = O_WD1; cin = 64;  cout = 128; }
        else if (i < O_W2B) { src = w2a; off = O_W2A; cin = 128; cout = 128; }
        else if (i < O_W2C) { src = w2b; off = O_W2B; cin = 128; cout = 128; }
        else                { src = w2c; off = O_W2C; cin = 128; cout = 128; }
        int r = i - off;
        int co = r % cout;
        int k  = (r / cout) % 27;
        int ci = r / (cout * 27);
        wt[i] = src[(co * cin + ci) * 27 + k];
    } else {
        int j = i - WT_TOTAL;
        if (j >= 736) return;
        const float* bn; int off, C, c;
        if      (j < 32)  { bn = b0a; off = OB_0A; C = 32;  c = j; }
        else if (j < 64)  { bn = b0b; off = OB_0B; C = 32;  c = j - 32; }
        else if (j < 96)  { bn = bd0; off = OB_D0; C = 32;  c = j - 64; }
        else if (j < 160) { bn = b1a; off = OB_1A; C = 64;  c = j - 96; }
        else if (j < 224) { bn = b1b; off = OB_1B; C = 64;  c = j - 160; }
        else if (j < 352) { bn = bd1; off = OB_D1; C = 128; c = j - 224; }
        else if (j < 480) { bn = b2a; off = OB_2A; C = 128; c = j - 352; }
        else if (j < 608) { bn = b2b; off = OB_2B; C = 128; c = j - 480; }
        else              { bn = b2c; off = OB_2C; C = 128; c = j - 608; }
        float g = bn[c], b = bn[C + c], mu = bn[2 * C + c], v = bn[3 * C + c];
        float s = g * rsqrtf(v + EPSV);
        bnf[off + 2 * c] = s;
        bnf[off + 2 * c + 1] = b - s * mu;
    }
}

// ----------------------------------------------------------------------------
// mask dtype probe (mode 0=u8 bool, 1=i32 bool, 2=f32, 3=bf16)
// ----------------------------------------------------------------------------
__global__ void probe_k(const unsigned char* __restrict__ b) {
    __shared__ int s_off1, s_big;
    if (threadIdx.x == 0) { s_off1 = 0; s_big = 0; }
    __syncthreads();
    int off1 = 0, big = 0;
    for (int i = threadIdx.x; i < 16384; i += blockDim.x) {
        unsigned char b0 = b[4 * i + 0], b1 = b[4 * i + 1];
        unsigned char b2 = b[4 * i + 2], b3 = b[4 * i + 3];
        if (b1) off1++;
        if (b0 > 1 || b1 > 1 || b2 > 1 || b3 > 1) big++;
    }
    atomicAdd(&s_off1, off1);
    atomicAdd(&s_big, big);
    __syncthreads();
    if (threadIdx.x == 0)
        g_mmode = (s_big == 0) ? ((s_off1 > 0) ? 0 : 1) : ((s_off1 > 0) ? 3 : 2);
}

__device__ __forceinline__ float mask_at(const unsigned char* b, int v, int mode) {
    if (mode == 0) return b[v] ? 1.f : 0.f;
    if (mode == 1) return ((const int*)b)[v] ? 1.f : 0.f;
    if (mode == 2) return (((const float*)b)[v] != 0.f) ? 1.f : 0.f;
    return (__bfloat162float(((const __nv_bfloat16*)b)[v]) != 0.f) ? 1.f : 0.f;
}

__global__ void premask_k(const float* __restrict__ x, const unsigned char* __restrict__ mb,
                          float* __restrict__ xm, float* __restrict__ m0) {
    int v = blockIdx.x * blockDim.x + threadIdx.x;
    if (v >= N0) return;
    int mode = g_mmode;
    float m = mask_at(mb, v, mode);
    m0[v] = m;
    int xx = v & 63, yy = (v >> 6) & 63, zz = v >> 12;
    int pidx = ((zz + 1) * PD0 + (yy + 1)) * PD0 + (xx + 1);
#pragma unroll
    for (int ci = 0; ci < 16; ci++) xm[ci * PD0_3 + pidx] = x[ci * N0 + v] * m;
}

template <int DIN>
__global__ void down_k(const float* __restrict__ mi, float* __restrict__ mo) {
    constexpr int DOUT = DIN / 2;
    int id = blockIdx.x * blockDim.x + threadIdx.x;
    if (id >= DOUT * DOUT * DOUT) return;
    int x = id % DOUT, y = (id / DOUT) % DOUT, z = id / (DOUT * DOUT);
    float m = 0.f;
#pragma unroll
    for (int dz = -1; dz <= 1; dz++) {
        int zz = 2 * z + dz; if ((unsigned)zz >= DIN) continue;
#pragma unroll
        for (int dy = -1; dy <= 1; dy++) {
            int yy = 2 * y + dy; if ((unsigned)yy >= DIN) continue;
#pragma unroll
            for (int dx = -1; dx <= 1; dx++) {
                int xx = 2 * x + dx; if ((unsigned)xx >= DIN) continue;
                m = fmaxf(m, mi[(zz * DIN + yy) * DIN + xx]);
            }
        }
    }
    mo[id] = m;
}

// ----------------------------------------------------------------------------
// FFMA2 stride-1 conv: XT=2, YT=2, CH=16 (8 co-pairs). Packed f32x2 math.
// ----------------------------------------------------------------------------
template <int CIN, int COUT, int SPLIT, int DIN, bool FUSE>
__global__ __launch_bounds__(128, 4) void conv2_k(const float* __restrict__ in,
                                                  const float* __restrict__ wt,
                                                  const float* __restrict__ bnf,
                                                  const float* __restrict__ mask,
                                                  float* __restrict__ out) {
    constexpr int DOUT = DIN;
    constexpr int PDI = DIN + 2;
    constexpr int PDI3 = PDI * PDI * PDI;
    constexpr int PDO = DIN + 2;
    constexpr int PDO3 = PDO * PDO * PDO;
    constexpr int CH = 16;
    constexpr int CHUNKS = COUT / CH;
    constexpr int CIB = CIN / SPLIT;

    int chunk = blockIdx.x % CHUNKS;
    int split = blockIdx.x / CHUNKS;
    int cb = chunk * CH;
    int x0 = 2 * threadIdx.x;
    int y0 = 2 * (blockIdx.y * blockDim.y + threadIdx.y);
    int z = blockIdx.z * blockDim.z + threadIdx.z;

    unsigned long long acc2[32];     // [vox(yt*2+xt)][co-pair 0..7]
#pragma unroll
    for (int i = 0; i < 32; i++) acc2[i] = 0ull;

    const float* base = in + split * CIB * PDI3 + (z * PDI + y0) * PDI + x0;
    const float* wp = wt + (split * CIB * 27) * COUT + cb;

    for (int ci = 0; ci < CIB; ci++) {
#pragma unroll
        for (int dz = 0; dz < 3; dz++) {
            unsigned long long pa[4][4];   // broadcast-packed taps [row][x]
#pragma unroll
            for (int r = 0; r < 4; r++) {
                const float2* rp2 = reinterpret_cast<const float2*>(base + (dz * PDI + r) * PDI);
                float2 t0 = __ldg(rp2 + 0);
                float2 t1 = __ldg(rp2 + 1);
                PACK2(pa[r][0], t0.x);
                PACK2(pa[r][1], t0.y);
                PACK2(pa[r][2], t1.x);
                PACK2(pa[r][3], t1.y);
            }
#pragma unroll
            for (int dy = 0; dy < 3; dy++)
#pragma unroll
                for (int dx = 0; dx < 3; dx++) {
                    const int k = (dz * 3 + dy) * 3 + dx;
                    const ulonglong2* w2p = reinterpret_cast<const ulonglong2*>(wp + k * COUT);
                    ulonglong2 wA = w2p[0];   // co pairs 0,1
                    ulonglong2 wB = w2p[1];   // co pairs 2,3
                    ulonglong2 wC = w2p[2];   // co pairs 4,5
                    ulonglong2 wD = w2p[3];   // co pairs 6,7
#pragma unroll
                    for (int yt = 0; yt < 2; yt++)
#pragma unroll
                        for (int xt = 0; xt < 2; xt++) {
                            unsigned long long a2 = pa[yt + dy][xt + dx];
                            const int o = (yt * 2 + xt) * 8;
                            FMA2(acc2[o + 0], a2, wA.x);
                            FMA2(acc2[o + 1], a2, wA.y);
                            FMA2(acc2[o + 2], a2, wB.x);
                            FMA2(acc2[o + 3], a2, wB.y);
                            FMA2(acc2[o + 4], a2, wC.x);
                            FMA2(acc2[o + 5], a2, wC.y);
                            FMA2(acc2[o + 6], a2, wD.x);
                            FMA2(acc2[o + 7], a2, wD.y);
                        }
                }
        }
        base += PDI3;
        wp += 27 * COUT;
    }

    if (FUSE) {
#pragma unroll
        for (int yt = 0; yt < 2; yt++) {
            int voxu = (z * DOUT + y0 + yt) * DOUT + x0;
            float mA = mask[voxu], mB = mask[voxu + 1];
            int pvox = ((z + 1) * PDO + (y0 + yt + 1)) * PDO + (x0 + 1);
#pragma unroll
            for (int cp = 0; cp < 8; cp++) {
                int c0 = cb + 2 * cp;
                float s0 = __ldg(bnf + 2 * c0),     t0 = __ldg(bnf + 2 * c0 + 1);
                float s1 = __ldg(bnf + 2 * c0 + 2), t1 = __ldg(bnf + 2 * c0 + 3);
                float lo, hi;
                UNPACK2(lo, hi, acc2[(yt * 2 + 0) * 8 + cp]);
                out[c0 * PDO3 + pvox]           = fmaxf(fmaf(s0, lo, t0), 0.f) * mA;
                out[(c0 + 1) * PDO3 + pvox]     = fmaxf(fmaf(s1, hi, t1), 0.f) * mA;
                UNPACK2(lo, hi, acc2[(yt * 2 + 1) * 8 + cp]);
                out[c0 * PDO3 + pvox + 1]       = fmaxf(fmaf(s0, lo, t0), 0.f) * mB;
                out[(c0 + 1) * PDO3 + pvox + 1] = fmaxf(fmaf(s1, hi, t1), 0.f) * mB;
            }
        }
    } else {
        constexpr int N = DOUT * DOUT * DOUT;
#pragma unroll
        for (int yt = 0; yt < 2; yt++) {
            int vox = (z * DOUT + y0 + yt) * DOUT + x0;
#pragma unroll
            for (int cp = 0; cp < 8; cp++) {
                int c0 = split * COUT + cb + 2 * cp;
                float lo, hi;
                UNPACK2(lo, hi, acc2[(yt * 2 + 0) * 8 + cp]);
                out[c0 * N + vox]           = lo;
                out[(c0 + 1) * N + vox]     = hi;
                UNPACK2(lo, hi, acc2[(yt * 2 + 1) * 8 + cp]);
                out[c0 * N + vox + 1]       = lo;
                out[(c0 + 1) * N + vox + 1] = hi;
            }
        }
    }
}

// ----------------------------------------------------------------------------
// scalar conv (stride-2 layers)
// ----------------------------------------------------------------------------
template <int CIN, int COUT, int STRIDE, int DIN, int SPLIT, int XT, int YT, int CH, bool FUSE>
__global__ __launch_bounds__(128, 4) void conv_k(const float* __restrict__ in,
                                                 const float* __restrict__ wt,
                                                 const float* __restrict__ bnf,
                                                 const float* __restrict__ mask,
                                                 float* __restrict__ out) {
    constexpr int DOUT = DIN / STRIDE;
    constexpr int PDI = DIN + 2;
    constexpr int PDI3 = PDI * PDI * PDI;
    constexpr int PDO = DOUT + 2;
    constexpr int PDO3 = PDO * PDO * PDO;
    constexpr int CHUNKS = COUT / CH;
    constexpr int CIB = CIN / SPLIT;
    constexpr int W = (XT - 1) * STRIDE + 3;
    constexpr int ROWS = (YT - 1) * STRIDE + 3;

    int tx = threadIdx.x, ty = threadIdx.y;
    int chunk = blockIdx.x % CHUNKS;
    int split = blockIdx.x / CHUNKS;
    int cb = chunk * CH;
    int y0 = (blockIdx.y * blockDim.y + ty) * YT;
    int z = blockIdx.z * blockDim.z + threadIdx.z;
    int x0 = XT * tx;

    float acc[YT * XT * CH];
#pragma unroll
    for (int i = 0; i < YT * XT * CH; i++) acc[i] = 0.f;

    const float* base = in + split * CIB * PDI3
                        + (z * STRIDE * PDI + y0 * STRIDE) * PDI + x0 * STRIDE;
    const float* wp = wt + (split * CIB * 27) * COUT + cb;

    for (int ci = 0; ci < CIB; ci++) {
#pragma unroll
        for (int dz = 0; dz < 3; dz++) {
            float v[ROWS][W];
#pragma unroll
            for (int r = 0; r < ROWS; r++) {
                const float* rp = base + (dz * PDI + r) * PDI;
                const float2* rp2 = reinterpret_cast<const float2*>(rp);
#pragma unroll
                for (int i = 0; i < W / 2; i++) {
                    float2 t = __ldg(rp2 + i);
                    v[r][2 * i] = t.x;
                    v[r][2 * i + 1] = t.y;
                }
                if (W & 1) v[r][W - 1] = __ldg(rp + W - 1);
            }
#pragma unroll
            for (int dy = 0; dy < 3; dy++)
#pragma unroll
                for (int dx = 0; dx < 3; dx++) {
                    const int k = (dz * 3 + dy) * 3 + dx;
                    const float4* w4 = reinterpret_cast<const float4*>(wp + k * COUT);
#pragma unroll
                    for (int j = 0; j < CH / 4; j++) {
                        float4 ww = __ldg(w4 + j);
#pragma unroll
                        for (int yt = 0; yt < YT; yt++)
#pragma unroll
                            for (int xt = 0; xt < XT; xt++) {
                                float a = v[yt * STRIDE + dy][xt * STRIDE + dx];
                                int o = (yt * XT + xt) * CH + 4 * j;
                                acc[o + 0] = fmaf(a, ww.x, acc[o + 0]);
                                acc[o + 1] = fmaf(a, ww.y, acc[o + 1]);
                                acc[o + 2] = fmaf(a, ww.z, acc[o + 2]);
                                acc[o + 3] = fmaf(a, ww.w, acc[o + 3]);
                            }
                    }
                }
        }
        base += PDI3;
        wp += 27 * COUT;
    }

    if (FUSE) {
#pragma unroll
        for (int yt = 0; yt < YT; yt++) {
            int voxu = (z * DOUT + y0 + yt) * DOUT + x0;
            float mm[XT];
#pragma unroll
            for (int xt = 0; xt < XT; xt++) mm[xt] = mask[voxu + xt];
            int pvox = ((z + 1) * PDO + (y0 + yt + 1)) * PDO + (x0 + 1);
#pragma unroll
            for (int i = 0; i < CH; i++) {
                int c = cb + i;
                float s = __ldg(bnf + 2 * c);
                float t = __ldg(bnf + 2 * c + 1);
#pragma unroll
                for (int xt = 0; xt < XT; xt++)
                    out[c * PDO3 + pvox + xt] =
                        fmaxf(fmaf(s, acc[(yt * XT + xt) * CH + i], t), 0.f) * mm[xt];
            }
        }
    } else {
        constexpr int N = DOUT * DOUT * DOUT;
#pragma unroll
        for (int yt = 0; yt < YT; yt++) {
            int vox = (z * DOUT + y0 + yt) * DOUT + x0;
#pragma unroll
            for (int i = 0; i < CH; i++) {
                int c = cb + i;
#pragma unroll
                for (int xt = 0; xt < XT; xt++)
                    out[(split * COUT + c) * N + vox + xt] = acc[(yt * XT + xt) * CH + i];
            }
        }
    }
}

// epilogue for split convs
template <int COUT, int DOUT, int SPLIT>
__global__ void epi_k(const float* __restrict__ part, const float* __restrict__ bnf,
                      const float* __restrict__ mask, float* __restrict__ out) {
    constexpr int N = DOUT * DOUT * DOUT;
    constexpr int PDO = DOUT + 2;
    constexpr int PDO3 = PDO * PDO * PDO;
    int id = blockIdx.x * blockDim.x + threadIdx.x;
    if (id >= COUT * N) return;
    int vox = id % N, c = id / N;
    float a = 0.f;
#pragma unroll
    for (int s = 0; s < SPLIT; s++) a += part[(s * COUT + c) * N + vox];
    float sc = __ldg(bnf + 2 * c), t = __ldg(bnf + 2 * c + 1);
    int x = vox % DOUT, y = (vox / DOUT) % DOUT, z = vox / (DOUT * DOUT);
    out[c * PDO3 + ((z + 1) * PDO + (y + 1)) * PDO + (x + 1)] =
        fmaxf(fmaf(sc, a, t), 0.f) * mask[vox];
}

// ----------------------------------------------------------------------------
// triplane means + sampler
// ----------------------------------------------------------------------------
__global__ void planes_k(const float* __restrict__ f, float* __restrict__ pl) {
    int id = blockIdx.x * blockDim.x + threadIdx.x;
    if (id >= 3 * 16 * 16 * 128) return;
    int c = id & 127;
    int rem = id >> 7;
    int b = rem & 15;
    int a = (rem >> 4) & 15;
    int t = rem >> 8;
    const float* fc = f + c * PD2_3;
    float s = 0.f;
    if (t == 0) {
#pragma unroll
        for (int z = 0; z < 16; z++) s += fc[((z + 1) * PD2 + (a + 1)) * PD2 + (b + 1)];
    } else if (t == 1) {
#pragma unroll
        for (int xx = 0; xx < 16; xx++) s += fc[((a + 1) * PD2 + (b + 1)) * PD2 + (xx + 1)];
    } else {
#pragma unroll
        for (int yy = 0; yy < 16; yy++) s += fc[((a + 1) * PD2 + (yy + 1)) * PD2 + (b + 1)];
    }
    pl[t * (16 * 16 * 128) + (a * 16 + b) * 128 + c] = s * (1.f / 16.f);
}

__device__ __forceinline__ float samp2d(const float* __restrict__ img, float gx, float gy, int c) {
    float ix = (gx + 1.f) * 0.5f * 15.f;
    float iy = (gy + 1.f) * 0.5f * 15.f;
    float x0f = floorf(ix), y0f = floorf(iy);
    int x0 = (int)x0f, y0 = (int)y0f;
    float wx = ix - x0f, wy = iy - y0f;
    float r = 0.f;
#pragma unroll
    for (int dy = 0; dy < 2; dy++)
#pragma unroll
        for (int dx = 0; dx < 2; dx++) {
            int xx = x0 + dx, yy = y0 + dy;
            float w = (dy ? wy : 1.f - wy) * (dx ? wx : 1.f - wx);
            bool ok = ((unsigned)xx < 16u) && ((unsigned)yy < 16u);
            int xc = min(max(xx, 0), 15), yc = min(max(yy, 0), 15);
            float v = __ldg(img + (yc * 16 + xc) * 128 + c);
            r += v * (ok ? w : 0.f);
        }
    return r;
}

__global__ void sample_k(const float* __restrict__ coords, const float* __restrict__ planes,
                         float* __restrict__ out) {
    constexpr int PTS = 16;
    int c = threadIdx.x;  // 128
    int p0 = blockIdx.x * PTS;
#pragma unroll 1
    for (int i = 0; i < PTS; i++) {
        int p = p0 + i;
        float c0 = __ldg(coords + 3 * p + 0);
        float c1 = __ldg(coords + 3 * p + 1);
        float c2 = __ldg(coords + 3 * p + 2);
        float s = samp2d(planes + 0 * (16 * 16 * 128), c0, c1, c)
                + samp2d(planes + 1 * (16 * 16 * 128), c1, c2, c)
                + samp2d(planes + 2 * (16 * 16 * 128), c0, c2, c);
        out[(size_t)p * 128 + c] = s;
    }
}

// ----------------------------------------------------------------------------
// launch — launch #4 is conv0a (ncu target)
// ----------------------------------------------------------------------------
extern "C" void kernel_launch(void* const* d_in, const int* in_sizes, int n_in,
                              void* d_out, int out_size) {
    const float* x = (const float*)d_in[0];
    const unsigned char* mask = (const unsigned char*)d_in[1];
    const float* coords = (const float*)d_in[2];
    const float* w0a = (const float*)d_in[3];  const float* bn0a = (const float*)d_in[4];
    const float* w0b = (const float*)d_in[5];  const float* bn0b = (const float*)d_in[6];
    const float* wd0 = (const float*)d_in[7];  const float* bnd0 = (const float*)d_in[8];
    const float* w1a = (const float*)d_in[9];  const float* bn1a = (const float*)d_in[10];
    const float* w1b = (const float*)d_in[11]; const float* bn1b = (const float*)d_in[12];
    const float* wd1 = (const float*)d_in[13]; const float* bnd1 = (const float*)d_in[14];
    const float* w2a = (const float*)d_in[15]; const float* bn2a = (const float*)d_in[16];
    const float* w2b = (const float*)d_in[17]; const float* bn2b = (const float*)d_in[18];
    const float* w2c = (const float*)d_in[19]; const float* bn2c = (const float*)d_in[20];

    float *xm, *A0, *B0, *A1, *B1, *A2, *B2, *part, *m0, *m1, *m2, *wt, *bnf, *pl;
    cudaGetSymbolAddress((void**)&xm, g_xm);
    cudaGetSymbolAddress((void**)&A0, g_A0);
    cudaGetSymbolAddress((void**)&B0, g_B0);
    cudaGetSymbolAddress((void**)&A1, g_A1);
    cudaGetSymbolAddress((void**)&B1, g_B1);
    cudaGetSymbolAddress((void**)&A2, g_A2);
    cudaGetSymbolAddress((void**)&B2, g_B2);
    cudaGetSymbolAddress((void**)&part, g_part);
    cudaGetSymbolAddress((void**)&m0, g_m0);
    cudaGetSymbolAddress((void**)&m1, g_m1);
    cudaGetSymbolAddress((void**)&m2, g_m2);
    cudaGetSymbolAddress((void**)&wt, g_wt);
    cudaGetSymbolAddress((void**)&bnf, g_bnf);
    cudaGetSymbolAddress((void**)&pl, g_planes);

    // 1-3: probe, merged prep, premask
    probe_k<<<1, 256>>>(mask);
    prep_k<<<(WT_TOTAL + 736 + 255) / 256, 256>>>(w0a, w0b, wd0, w1a, w1b, wd1, w2a, w2b, w2c,
                                                  bn0a, bn0b, bnd0, bn1a, bn1b, bnd1, bn2a, bn2b, bn2c,
                                                  wt, bnf);
    premask_k<<<(N0 + 255) / 256, 256>>>(x, mask, xm, m0);

    // 4-6: conv0a (ncu target), conv0b, convd0
    conv2_k<16, 32, 1, 64, true><<<dim3(2, 8, 64), dim3(32, 4)>>>(xm, wt + O_W0A, bnf + OB_0A, m0, A0);
    conv2_k<32, 32, 1, 64, true><<<dim3(2, 8, 64), dim3(32, 4)>>>(A0, wt + O_W0B, bnf + OB_0B, m0, B0);
    conv_k<32, 32, 2, 64, 2, 2, 1, 16, false><<<dim3(4, 4, 32), dim3(16, 8)>>>(B0, wt + O_WD0, nullptr, nullptr, part);

    // 7-9: mask downsamples + epi_d0
    down_k<64><<<(N1 + 255) / 256, 256>>>(m0, m1);
    epi_k<32, 32, 2><<<(32 * N1 + 255) / 256, 256>>>(part, bnf + OB_D0, m1, A1);
    down_k<32><<<(N2 + 255) / 256, 256>>>(m1, m2);

    // 10-13: stage 1 @32^3 + downsample 1
    conv2_k<32, 64, 1, 32, true><<<dim3(4, 2, 32), dim3(16, 8)>>>(A1, wt + O_W1A, bnf + OB_1A, m1, B1);
    conv2_k<64, 64, 1, 32, true><<<dim3(4, 2, 32), dim3(16, 8)>>>(B1, wt + O_W1B, bnf + OB_1B, m1, A1);
    conv_k<64, 128, 2, 32, 4, 2, 1, 16, false><<<dim3(32, 1, 16), dim3(8, 16)>>>(A1, wt + O_WD1, nullptr, nullptr, part);
    epi_k<128, 16, 4><<<(128 * N2 + 255) / 256, 256>>>(part, bnf + OB_D1, m2, A2);

    // 14-19: stage 2 @16^3 (split 4)
    conv2_k<128, 128, 4, 16, false><<<dim3(32, 1, 8), dim3(8, 8, 2)>>>(A2, wt + O_W2A, nullptr, nullptr, part);
    epi_k<128, 16, 4><<<(128 * N2 + 255) / 256, 256>>>(part, bnf + OB_2A, m2, B2);
    conv2_k<128, 128, 4, 16, false><<<dim3(32, 1, 8), dim3(8, 8, 2)>>>(B2, wt + O_W2B, nullptr, nullptr, part);
    epi_k<128, 16, 4><<<(128 * N2 + 255) / 256, 256>>>(part, bnf + OB_2B, m2, A2);
    conv2_k<128, 128, 4, 16, false><<<dim3(32, 1, 8), dim3(8, 8, 2)>>>(A2, wt + O_W2C, nullptr, nullptr, part);
    epi_k<128, 16, 4><<<(128 * N2 + 255) / 256, 256>>>(part, bnf + OB_2C, m2, B2);

    // 20-21: triplane + sample
    planes_k<<<(3 * 16 * 16 * 128 + 255) / 256, 256>>>(B2, pl);
    sample_k<<<NPTS / 16, 128>>>(coords, pl, (float*)d_out);
}

// round 11
// speedup vs baseline: 1.1140x; 1.1140x over previous
#include <cuda_runtime.h>
#include <cuda_bf16.h>
#include <cstdint>

// ============================================================================
// SparseConvNet_Triplane v7: v5 scalar conv core (best known) + 64-thread
// blocks for stage-1/stage-2 convs (deeper per-SM warp pools).
// ============================================================================

#define EPSV 1e-3f

static constexpr int N0 = 64 * 64 * 64;
static constexpr int N1 = 32 * 32 * 32;
static constexpr int N2 = 16 * 16 * 16;
static constexpr int NPTS = 65536;

static constexpr int PD0 = 66, PD0_3 = PD0 * PD0 * PD0;
static constexpr int PD1 = 34, PD1_3 = PD1 * PD1 * PD1;
static constexpr int PD2 = 18, PD2_3 = PD2 * PD2 * PD2;

// weight segments, layout [ci][k][co]
static constexpr int O_W0A = 0;
static constexpr int O_W0B = O_W0A + 16 * 32 * 27;
static constexpr int O_WD0 = O_W0B + 32 * 32 * 27;
static constexpr int O_W1A = O_WD0 + 32 * 32 * 27;
static constexpr int O_W1B = O_W1A + 32 * 64 * 27;
static constexpr int O_WD1 = O_W1B + 64 * 64 * 27;
static constexpr int O_W2A = O_WD1 + 64 * 128 * 27;
static constexpr int O_W2B = O_W2A + 128 * 128 * 27;
static constexpr int O_W2C = O_W2B + 128 * 128 * 27;
static constexpr int WT_TOTAL = O_W2C + 128 * 128 * 27;

// fused BN scale/shift segments
static constexpr int OB_0A = 0;
static constexpr int OB_0B = OB_0A + 2 * 32;
static constexpr int OB_D0 = OB_0B + 2 * 32;
static constexpr int OB_1A = OB_D0 + 2 * 32;
static constexpr int OB_1B = OB_1A + 2 * 64;
static constexpr int OB_D1 = OB_1B + 2 * 64;
static constexpr int OB_2A = OB_D1 + 2 * 128;
static constexpr int OB_2B = OB_2A + 2 * 128;
static constexpr int OB_2C = OB_2B + 2 * 128;
static constexpr int BNF_TOTAL = OB_2C + 2 * 128;

// static scratch; halos of padded buffers never written -> stay 0
__device__ __align__(16) float g_xm[16 * PD0_3];
__device__ __align__(16) float g_A0[32 * PD0_3];
__device__ __align__(16) float g_B0[32 * PD0_3];
__device__ __align__(16) float g_A1[64 * PD1_3];
__device__ __align__(16) float g_B1[64 * PD1_3];
__device__ __align__(16) float g_A2[128 * PD2_3];
__device__ __align__(16) float g_B2[128 * PD2_3];
__device__ __align__(16) float g_part[2097152];
__device__ float g_m0[N0];
__device__ float g_m1[N1];
__device__ float g_m2[N2];
__device__ __align__(16) float g_wt[WT_TOTAL];
__device__ __align__(16) float g_bnf[BNF_TOTAL];
__device__ __align__(16) float g_planes[3 * 16 * 16 * 128];
__device__ int g_mmode;

// ----------------------------------------------------------------------------
// merged prep: weight transposes + BN fusion
// ----------------------------------------------------------------------------
__global__ void prep_k(const float* __restrict__ w0a, const float* __restrict__ w0b,
                       const float* __restrict__ wd0, const float* __restrict__ w1a,
                       const float* __restrict__ w1b, const float* __restrict__ wd1,
                       const float* __restrict__ w2a, const float* __restrict__ w2b,
                       const float* __restrict__ w2c,
                       const float* __restrict__ b0a, const float* __restrict__ b0b,
                       const float* __restrict__ bd0, const float* __restrict__ b1a,
                       const float* __restrict__ b1b, const float* __restrict__ bd1,
                       const float* __restrict__ b2a, const float* __restrict__ b2b,
                       const float* __restrict__ b2c,
                       float* __restrict__ wt, float* __restrict__ bnf) {
    int i = blockIdx.x * blockDim.x + threadIdx.x;
    if (i < WT_TOTAL) {
        const float* src; int off, cin, cout;
        if      (i < O_W0B) { src = w0a; off = O_W0A; cin = 16;  cout = 32; }
        else if (i < O_WD0) { src = w0b; off = O_W0B; cin = 32;  cout = 32; }
        else if (i < O_W1A) { src = wd0; off = O_WD0; cin = 32;  cout = 32; }
        else if (i < O_W1B) { src = w1a; off = O_W1A; cin = 32;  cout = 64; }
        else if (i < O_WD1) { src = w1b; off = O_W1B; cin = 64;  cout = 64; }
        else if (i < O_W2A) { src = wd1; off = O_WD1; cin = 64;  cout = 128; }
        else if (i < O_W2B) { src = w2a; off = O_W2A; cin = 128; cout = 128; }
        else if (i < O_W2C) { src = w2b; off = O_W2B; cin = 128; cout = 128; }
        else                { src = w2c; off = O_W2C; cin = 128; cout = 128; }
        int r = i - off;
        int co = r % cout;
        int k  = (r / cout) % 27;
        int ci = r / (cout * 27);
        wt[i] = src[(co * cin + ci) * 27 + k];
    } else {
        int j = i - WT_TOTAL;
        if (j >= 736) return;
        const float* bn; int off, C, c;
        if      (j < 32)  { bn = b0a; off = OB_0A; C = 32;  c = j; }
        else if (j < 64)  { bn = b0b; off = OB_0B; C = 32;  c = j - 32; }
        else if (j < 96)  { bn = bd0; off = OB_D0; C = 32;  c = j - 64; }
        else if (j < 160) { bn = b1a; off = OB_1A; C = 64;  c = j - 96; }
        else if (j < 224) { bn = b1b; off = OB_1B; C = 64;  c = j - 160; }
        else if (j < 352) { bn = bd1; off = OB_D1; C = 128; c = j - 224; }
        else if (j < 480) { bn = b2a; off = OB_2A; C = 128; c = j - 352; }
        else if (j < 608) { bn = b2b; off = OB_2B; C = 128; c = j - 480; }
        else              { bn = b2c; off = OB_2C; C = 128; c = j - 608; }
        float g = bn[c], b = bn[C + c], mu = bn[2 * C + c], v = bn[3 * C + c];
        float s = g * rsqrtf(v + EPSV);
        bnf[off + 2 * c] = s;
        bnf[off + 2 * c + 1] = b - s * mu;
    }
}

// ----------------------------------------------------------------------------
// mask dtype probe (mode 0=u8 bool, 1=i32 bool, 2=f32, 3=bf16)
// ----------------------------------------------------------------------------
__global__ void probe_k(const unsigned char* __restrict__ b) {
    __shared__ int s_off1, s_big;
    if (threadIdx.x == 0) { s_off1 = 0; s_big = 0; }
    __syncthreads();
    int off1 = 0, big = 0;
    for (int i = threadIdx.x; i < 16384; i += blockDim.x) {
        unsigned char b0 = b[4 * i + 0], b1 = b[4 * i + 1];
        unsigned char b2 = b[4 * i + 2], b3 = b[4 * i + 3];
        if (b1) off1++;
        if (b0 > 1 || b1 > 1 || b2 > 1 || b3 > 1) big++;
    }
    atomicAdd(&s_off1, off1);
    atomicAdd(&s_big, big);
    __syncthreads();
    if (threadIdx.x == 0)
        g_mmode = (s_big == 0) ? ((s_off1 > 0) ? 0 : 1) : ((s_off1 > 0) ? 3 : 2);
}

__device__ __forceinline__ float mask_at(const unsigned char* b, int v, int mode) {
    if (mode == 0) return b[v] ? 1.f : 0.f;
    if (mode == 1) return ((const int*)b)[v] ? 1.f : 0.f;
    if (mode == 2) return (((const float*)b)[v] != 0.f) ? 1.f : 0.f;
    return (__bfloat162float(((const __nv_bfloat16*)b)[v]) != 0.f) ? 1.f : 0.f;
}

__global__ void premask_k(const float* __restrict__ x, const unsigned char* __restrict__ mb,
                          float* __restrict__ xm, float* __restrict__ m0) {
    int v = blockIdx.x * blockDim.x + threadIdx.x;
    if (v >= N0) return;
    int mode = g_mmode;
    float m = mask_at(mb, v, mode);
    m0[v] = m;
    int xx = v & 63, yy = (v >> 6) & 63, zz = v >> 12;
    int pidx = ((zz + 1) * PD0 + (yy + 1)) * PD0 + (xx + 1);
#pragma unroll
    for (int ci = 0; ci < 16; ci++) xm[ci * PD0_3 + pidx] = x[ci * N0 + v] * m;
}

template <int DIN>
__global__ void down_k(const float* __restrict__ mi, float* __restrict__ mo) {
    constexpr int DOUT = DIN / 2;
    int id = blockIdx.x * blockDim.x + threadIdx.x;
    if (id >= DOUT * DOUT * DOUT) return;
    int x = id % DOUT, y = (id / DOUT) % DOUT, z = id / (DOUT * DOUT);
    float m = 0.f;
#pragma unroll
    for (int dz = -1; dz <= 1; dz++) {
        int zz = 2 * z + dz; if ((unsigned)zz >= DIN) continue;
#pragma unroll
        for (int dy = -1; dy <= 1; dy++) {
            int yy = 2 * y + dy; if ((unsigned)yy >= DIN) continue;
#pragma unroll
            for (int dx = -1; dx <= 1; dx++) {
                int xx = 2 * x + dx; if ((unsigned)xx >= DIN) continue;
                m = fmaxf(m, mi[(zz * DIN + yy) * DIN + xx]);
            }
        }
    }
    mo[id] = m;
}

// ----------------------------------------------------------------------------
// conv 3^3 on padded buffers. XT x YT output patch per thread, CH channels.
// ----------------------------------------------------------------------------
template <int CIN, int COUT, int STRIDE, int DIN, int SPLIT, int XT, int YT, int CH, bool FUSE>
__global__ __launch_bounds__(128, 4) void conv_k(const float* __restrict__ in,
                                                 const float* __restrict__ wt,
                                                 const float* __restrict__ bnf,
                                                 const float* __restrict__ mask,
                                                 float* __restrict__ out) {
    constexpr int DOUT = DIN / STRIDE;
    constexpr int PDI = DIN + 2;
    constexpr int PDI3 = PDI * PDI * PDI;
    constexpr int PDO = DOUT + 2;
    constexpr int PDO3 = PDO * PDO * PDO;
    constexpr int CHUNKS = COUT / CH;
    constexpr int CIB = CIN / SPLIT;
    constexpr int W = (XT - 1) * STRIDE + 3;
    constexpr int ROWS = (YT - 1) * STRIDE + 3;

    int tx = threadIdx.x, ty = threadIdx.y;
    int chunk = blockIdx.x % CHUNKS;
    int split = blockIdx.x / CHUNKS;
    int cb = chunk * CH;
    int y0 = (blockIdx.y * blockDim.y + ty) * YT;
    int z = blockIdx.z * blockDim.z + threadIdx.z;
    int x0 = XT * tx;

    float acc[YT * XT * CH];
#pragma unroll
    for (int i = 0; i < YT * XT * CH; i++) acc[i] = 0.f;

    const float* base = in + split * CIB * PDI3
                        + (z * STRIDE * PDI + y0 * STRIDE) * PDI + x0 * STRIDE;
    const float* wp = wt + (split * CIB * 27) * COUT + cb;

    for (int ci = 0; ci < CIB; ci++) {
#pragma unroll
        for (int dz = 0; dz < 3; dz++) {
            float v[ROWS][W];
#pragma unroll
            for (int r = 0; r < ROWS; r++) {
                const float* rp = base + (dz * PDI + r) * PDI;
                const float2* rp2 = reinterpret_cast<const float2*>(rp);
#pragma unroll
                for (int i = 0; i < W / 2; i++) {
                    float2 t = __ldg(rp2 + i);
                    v[r][2 * i] = t.x;
                    v[r][2 * i + 1] = t.y;
                }
                if (W & 1) v[r][W - 1] = __ldg(rp + W - 1);
            }
#pragma unroll
            for (int dy = 0; dy < 3; dy++)
#pragma unroll
                for (int dx = 0; dx < 3; dx++) {
                    const int k = (dz * 3 + dy) * 3 + dx;
                    const float4* w4 = reinterpret_cast<const float4*>(wp + k * COUT);
#pragma unroll
                    for (int j = 0; j < CH / 4; j++) {
                        float4 ww = __ldg(w4 + j);
#pragma unroll
                        for (int yt = 0; yt < YT; yt++)
#pragma unroll
                            for (int xt = 0; xt < XT; xt++) {
                                float a = v[yt * STRIDE + dy][xt * STRIDE + dx];
                                int o = (yt * XT + xt) * CH + 4 * j;
                                acc[o + 0] = fmaf(a, ww.x, acc[o + 0]);
                                acc[o + 1] = fmaf(a, ww.y, acc[o + 1]);
                                acc[o + 2] = fmaf(a, ww.z, acc[o + 2]);
                                acc[o + 3] = fmaf(a, ww.w, acc[o + 3]);
                            }
                    }
                }
        }
        base += PDI3;
        wp += 27 * COUT;
    }

    if (FUSE) {
#pragma unroll
        for (int yt = 0; yt < YT; yt++) {
            int voxu = (z * DOUT + y0 + yt) * DOUT + x0;
            float mm[XT];
#pragma unroll
            for (int xt = 0; xt < XT; xt++) mm[xt] = mask[voxu + xt];
            int pvox = ((z + 1) * PDO + (y0 + yt + 1)) * PDO + (x0 + 1);
#pragma unroll
            for (int i = 0; i < CH; i++) {
                int c = cb + i;
                float s = __ldg(bnf + 2 * c);
                float t = __ldg(bnf + 2 * c + 1);
#pragma unroll
                for (int xt = 0; xt < XT; xt++)
                    out[c * PDO3 + pvox + xt] =
                        fmaxf(fmaf(s, acc[(yt * XT + xt) * CH + i], t), 0.f) * mm[xt];
            }
        }
    } else {
        constexpr int N = DOUT * DOUT * DOUT;
#pragma unroll
        for (int yt = 0; yt < YT; yt++) {
            int vox = (z * DOUT + y0 + yt) * DOUT + x0;
#pragma unroll
            for (int i = 0; i < CH; i++) {
                int c = cb + i;
#pragma unroll
                for (int xt = 0; xt < XT; xt++)
                    out[(split * COUT + c) * N + vox + xt] = acc[(yt * XT + xt) * CH + i];
            }
        }
    }
}

// epilogue for split convs
template <int COUT, int DOUT, int SPLIT>
__global__ void epi_k(const float* __restrict__ part, const float* __restrict__ bnf,
                      const float* __restrict__ mask, float* __restrict__ out) {
    constexpr int N = DOUT * DOUT * DOUT;
    constexpr int PDO = DOUT + 2;
    constexpr int PDO3 = PDO * PDO * PDO;
    int id = blockIdx.x * blockDim.x + threadIdx.x;
    if (id >= COUT * N) return;
    int vox = id % N, c = id / N;
    float a = 0.f;
#pragma unroll
    for (int s = 0; s < SPLIT; s++) a += part[(s * COUT + c) * N + vox];
    float sc = __ldg(bnf + 2 * c), t = __ldg(bnf + 2 * c + 1);
    int x = vox % DOUT, y = (vox / DOUT) % DOUT, z = vox / (DOUT * DOUT);
    out[c * PDO3 + ((z + 1) * PDO + (y + 1)) * PDO + (x + 1)] =
        fmaxf(fmaf(sc, a, t), 0.f) * mask[vox];
}

// ----------------------------------------------------------------------------
// triplane means + sampler
// ----------------------------------------------------------------------------
__global__ void planes_k(const float* __restrict__ f, float* __restrict__ pl) {
    int id = blockIdx.x * blockDim.x + threadIdx.x;
    if (id >= 3 * 16 * 16 * 128) return;
    int c = id & 127;
    int rem = id >> 7;
    int b = rem & 15;
    int a = (rem >> 4) & 15;
    int t = rem >> 8;
    const float* fc = f + c * PD2_3;
    float s = 0.f;
    if (t == 0) {
#pragma unroll
        for (int z = 0; z < 16; z++) s += fc[((z + 1) * PD2 + (a + 1)) * PD2 + (b + 1)];
    } else if (t == 1) {
#pragma unroll
        for (int xx = 0; xx < 16; xx++) s += fc[((a + 1) * PD2 + (b + 1)) * PD2 + (xx + 1)];
    } else {
#pragma unroll
        for (int yy = 0; yy < 16; yy++) s += fc[((a + 1) * PD2 + (yy + 1)) * PD2 + (b + 1)];
    }
    pl[t * (16 * 16 * 128) + (a * 16 + b) * 128 + c] = s * (1.f / 16.f);
}

__device__ __forceinline__ float samp2d(const float* __restrict__ img, float gx, float gy, int c) {
    float ix = (gx + 1.f) * 0.5f * 15.f;
    float iy = (gy + 1.f) * 0.5f * 15.f;
    float x0f = floorf(ix), y0f = floorf(iy);
    int x0 = (int)x0f, y0 = (int)y0f;
    float wx = ix - x0f, wy = iy - y0f;
    float r = 0.f;
#pragma unroll
    for (int dy = 0; dy < 2; dy++)
#pragma unroll
        for (int dx = 0; dx < 2; dx++) {
            int xx = x0 + dx, yy = y0 + dy;
            float w = (dy ? wy : 1.f - wy) * (dx ? wx : 1.f - wx);
            bool ok = ((unsigned)xx < 16u) && ((unsigned)yy < 16u);
            int xc = min(max(xx, 0), 15), yc = min(max(yy, 0), 15);
            float v = __ldg(img + (yc * 16 + xc) * 128 + c);
            r += v * (ok ? w : 0.f);
        }
    return r;
}

__global__ void sample_k(const float* __restrict__ coords, const float* __restrict__ planes,
                         float* __restrict__ out) {
    constexpr int PTS = 16;
    int c = threadIdx.x;  // 128
    int p0 = blockIdx.x * PTS;
#pragma unroll 1
    for (int i = 0; i < PTS; i++) {
        int p = p0 + i;
        float c0 = __ldg(coords + 3 * p + 0);
        float c1 = __ldg(coords + 3 * p + 1);
        float c2 = __ldg(coords + 3 * p + 2);
        float s = samp2d(planes + 0 * (16 * 16 * 128), c0, c1, c)
                + samp2d(planes + 1 * (16 * 16 * 128), c1, c2, c)
                + samp2d(planes + 2 * (16 * 16 * 128), c0, c2, c);
        out[(size_t)p * 128 + c] = s;
    }
}

// ----------------------------------------------------------------------------
// launch — launch #4 is conv0a (ncu target)
// ----------------------------------------------------------------------------
extern "C" void kernel_launch(void* const* d_in, const int* in_sizes, int n_in,
                              void* d_out, int out_size) {
    const float* x = (const float*)d_in[0];
    const unsigned char* mask = (const unsigned char*)d_in[1];
    const float* coords = (const float*)d_in[2];
    const float* w0a = (const float*)d_in[3];  const float* bn0a = (const float*)d_in[4];
    const float* w0b = (const float*)d_in[5];  const float* bn0b = (const float*)d_in[6];
    const float* wd0 = (const float*)d_in[7];  const float* bnd0 = (const float*)d_in[8];
    const float* w1a = (const float*)d_in[9];  const float* bn1a = (const float*)d_in[10];
    const float* w1b = (const float*)d_in[11]; const float* bn1b = (const float*)d_in[12];
    const float* wd1 = (const float*)d_in[13]; const float* bnd1 = (const float*)d_in[14];
    const float* w2a = (const float*)d_in[15]; const float* bn2a = (const float*)d_in[16];
    const float* w2b = (const float*)d_in[17]; const float* bn2b = (const float*)d_in[18];
    const float* w2c = (const float*)d_in[19]; const float* bn2c = (const float*)d_in[20];

    float *xm, *A0, *B0, *A1, *B1, *A2, *B2, *part, *m0, *m1, *m2, *wt, *bnf, *pl;
    cudaGetSymbolAddress((void**)&xm, g_xm);
    cudaGetSymbolAddress((void**)&A0, g_A0);
    cudaGetSymbolAddress((void**)&B0, g_B0);
    cudaGetSymbolAddress((void**)&A1, g_A1);
    cudaGetSymbolAddress((void**)&B1, g_B1);
    cudaGetSymbolAddress((void**)&A2, g_A2);
    cudaGetSymbolAddress((void**)&B2, g_B2);
    cudaGetSymbolAddress((void**)&part, g_part);
    cudaGetSymbolAddress((void**)&m0, g_m0);
    cudaGetSymbolAddress((void**)&m1, g_m1);
    cudaGetSymbolAddress((void**)&m2, g_m2);
    cudaGetSymbolAddress((void**)&wt, g_wt);
    cudaGetSymbolAddress((void**)&bnf, g_bnf);
    cudaGetSymbolAddress((void**)&pl, g_planes);

    // 1-3: probe, merged prep, premask
    probe_k<<<1, 256>>>(mask);
    prep_k<<<(WT_TOTAL + 736 + 255) / 256, 256>>>(w0a, w0b, wd0, w1a, w1b, wd1, w2a, w2b, w2c,
                                                  bn0a, bn0b, bnd0, bn1a, bn1b, bnd1, bn2a, bn2b, bn2c,
                                                  wt, bnf);
    premask_k<<<(N0 + 255) / 256, 256>>>(x, mask, xm, m0);

    // 4-6: conv0a (ncu target), conv0b, convd0  — identical to v5
    conv_k<16, 32, 1, 64, 1, 4, 2, 8, true><<<dim3(4, 4, 64), dim3(16, 8)>>>(xm, wt + O_W0A, bnf + OB_0A, m0, A0);
    conv_k<32, 32, 1, 64, 1, 4, 2, 8, true><<<dim3(4, 4, 64), dim3(16, 8)>>>(A0, wt + O_W0B, bnf + OB_0B, m0, B0);
    conv_k<32, 32, 2, 64, 2, 2, 1, 16, false><<<dim3(4, 4, 32), dim3(16, 8)>>>(B0, wt + O_WD0, nullptr, nullptr, part);

    // 7-9: mask downsamples + epi_d0
    down_k<64><<<(N1 + 255) / 256, 256>>>(m0, m1);
    epi_k<32, 32, 2><<<(32 * N1 + 255) / 256, 256>>>(part, bnf + OB_D0, m1, A1);
    down_k<32><<<(N2 + 255) / 256, 256>>>(m1, m2);

    // 10-13: stage 1 @32^3 — 64-thread blocks, 512 blocks (deeper warp pools)
    conv_k<32, 64, 1, 32, 1, 4, 2, 8, true><<<dim3(8, 2, 32), dim3(8, 8)>>>(A1, wt + O_W1A, bnf + OB_1A, m1, B1);
    conv_k<64, 64, 1, 32, 1, 4, 2, 8, true><<<dim3(8, 2, 32), dim3(8, 8)>>>(B1, wt + O_W1B, bnf + OB_1B, m1, A1);
    conv_k<64, 128, 2, 32, 4, 2, 1, 16, false><<<dim3(32, 1, 16), dim3(8, 16)>>>(A1, wt + O_WD1, nullptr, nullptr, part);
    epi_k<128, 16, 4><<<(128 * N2 + 255) / 256, 256>>>(part, bnf + OB_D1, m2, A2);

    // 14-19: stage 2 @16^3 — 64-thread blocks, 512 blocks each
    conv_k<128, 128, 1, 16, 4, 4, 2, 8, false><<<dim3(64, 1, 8), dim3(4, 8, 2)>>>(A2, wt + O_W2A, nullptr, nullptr, part);
    epi_k<128, 16, 4><<<(128 * N2 + 255) / 256, 256>>>(part, bnf + OB_2A, m2, B2);
    conv_k<128, 128, 1, 16, 4, 4, 2, 8, false><<<dim3(64, 1, 8), dim3(4, 8, 2)>>>(B2, wt + O_W2B, nullptr, nullptr, part);
    epi_k<128, 16, 4><<<(128 * N2 + 255) / 256, 256>>>(part, bnf + OB_2B, m2, A2);
    conv_k<128, 128, 1, 16, 4, 4, 2, 8, false><<<dim3(64, 1, 8), dim3(4, 8, 2)>>>(A2, wt + O_W2C, nullptr, nullptr, part);
    epi_k<128, 16, 4><<<(128 * N2 + 255) / 256, 256>>>(part, bnf + OB_2C, m2, B2);

    // 20-21: triplane + sample
    planes_k<<<(3 * 16 * 16 * 128 + 255) / 256, 256>>>(B2, pl);
    sample_k<<<NPTS / 16, 128>>>(coords, pl, (float*)d_out);
}